// round 1
// baseline (speedup 1.0000x reference)
#include <cuda_runtime.h>
#include <cstdint>

// ---------------- Problem constants ----------------
#define BATCH    256
#define D_MODEL  2048
#define D_STATE  128
#define D_CONV   4
#define D_SSM    4096
#define NHEADS   64
#define HEADDIM  64
#define CONV_DIM (D_SSM + 2 * D_STATE)           // 4352
#define D_IN_PROJ (2 * D_SSM + 2 * D_STATE + NHEADS) // 8512

// zxbcdt row layout: [0,4096)=z  [4096,8448)=xBC  [8448,8512)=dt
#define OFF_XBC  D_SSM
#define OFF_DT   (D_SSM + CONV_DIM)
// xbc_act row layout: [0,4096)=x [4096,4224)=B [4224,4352)=C

// d_out layout: out(256*2048) | conv_state(256*4352*4) | ssm_state(256*64*64*128)
#define OUT_ELEMS   (BATCH * D_MODEL)                 // 524288
#define CONV_ELEMS  (BATCH * CONV_DIM * D_CONV)       // 4456448

// ---------------- Scratch (__device__ globals; no allocs allowed) ----------------
__device__ float g_zxbcdt[BATCH * D_IN_PROJ];   // 8.7 MB
__device__ float g_xbc[BATCH * CONV_DIM];       // 4.5 MB (activated x|B|C)
__device__ float g_yact[BATCH * D_SSM];         // 4.2 MB (y * silu(z))

// ---------------- f32x2 packed-FMA helpers ----------------
__device__ __forceinline__ void fma2(unsigned long long& d, unsigned long long a,
                                     unsigned long long b) {
    asm("fma.rn.f32x2 %0, %1, %2, %0;" : "+l"(d) : "l"(a), "l"(b));
}
__device__ __forceinline__ unsigned long long dup_f(float x) {
    unsigned long long r;
    asm("mov.b64 %0, {%1, %1};" : "=l"(r) : "r"(__float_as_uint(x)));
    return r;
}
__device__ __forceinline__ unsigned long long pack2(float lo, float hi) {
    unsigned long long r;
    asm("mov.b64 %0, {%1, %2};" : "=l"(r) : "r"(__float_as_uint(lo)), "r"(__float_as_uint(hi)));
    return r;
}

// ---------------- GEMM: C[m,n] = sum_k A[m*K+k] * W[n*K+k]  (both K-major "NT") ----------------
template <int M, int N, int K, int BM, int BN, int BK, int TM, int TN>
__global__ void __launch_bounds__((BM / TM) * (BN / TN))
sgemm_nt(const float* __restrict__ A, const float* __restrict__ W, float* __restrict__ C) {
    constexpr int THREADS = (BM / TM) * (BN / TN);
    __shared__ float As[BK][BM + 4];
    __shared__ float Ws[BK][BN + 4];

    const int tid = threadIdx.x;
    const int tn  = tid % (BN / TN);
    const int tm  = tid / (BN / TN);
    const int mBase = blockIdx.y * BM;
    const int nBase = blockIdx.x * BN;

    unsigned long long acc[TM][TN / 2];
#pragma unroll
    for (int i = 0; i < TM; i++)
#pragma unroll
        for (int j = 0; j < TN / 2; j++) acc[i][j] = 0ull;

    constexpr int A_LD = (BM * BK / 4) / THREADS;
    constexpr int W_LD = (BN * BK / 4) / THREADS;

    for (int kk = 0; kk < K; kk += BK) {
#pragma unroll
        for (int i = 0; i < A_LD; i++) {
            int id  = tid + i * THREADS;
            int row = id / (BK / 4);
            int kc  = id % (BK / 4);
            float4 v = *(const float4*)(A + (size_t)(mBase + row) * K + kk + kc * 4);
            As[kc * 4 + 0][row] = v.x;
            As[kc * 4 + 1][row] = v.y;
            As[kc * 4 + 2][row] = v.z;
            As[kc * 4 + 3][row] = v.w;
        }
#pragma unroll
        for (int i = 0; i < W_LD; i++) {
            int id  = tid + i * THREADS;
            int row = id / (BK / 4);
            int kc  = id % (BK / 4);
            float4 v = *(const float4*)(W + (size_t)(nBase + row) * K + kk + kc * 4);
            Ws[kc * 4 + 0][row] = v.x;
            Ws[kc * 4 + 1][row] = v.y;
            Ws[kc * 4 + 2][row] = v.z;
            Ws[kc * 4 + 3][row] = v.w;
        }
        __syncthreads();
#pragma unroll
        for (int k = 0; k < BK; k++) {
            unsigned long long bfrag[TN / 2];
#pragma unroll
            for (int j = 0; j < TN / 2; j++) {
                float2 bv = *(const float2*)&Ws[k][tn * TN + 2 * j];
                bfrag[j]  = pack2(bv.x, bv.y);
            }
#pragma unroll
            for (int i = 0; i < TM; i++) {
                unsigned long long ad = dup_f(As[k][tm * TM + i]);
#pragma unroll
                for (int j = 0; j < TN / 2; j++) fma2(acc[i][j], ad, bfrag[j]);
            }
        }
        __syncthreads();
    }

#pragma unroll
    for (int i = 0; i < TM; i++) {
#pragma unroll
        for (int j = 0; j < TN / 2; j++) {
            union { unsigned long long u; float2 f; } cv;
            cv.u = acc[i][j];
            *(float2*)(C + (size_t)(mBase + tm * TM + i) * N + nBase + tn * TN + 2 * j) = cv.f;
        }
    }
}

// ---------------- Conv: roll state, 4-tap conv + bias, SiLU ----------------
__global__ void conv_kernel(const float* __restrict__ conv_in,
                            const float* __restrict__ conv_w,
                            const float* __restrict__ conv_b,
                            float* __restrict__ conv_out) {
    int idx = blockIdx.x * blockDim.x + threadIdx.x;
    if (idx >= BATCH * CONV_DIM) return;
    int b = idx / CONV_DIM;
    int c = idx % CONV_DIM;

    float4 s = *(const float4*)(conv_in + (size_t)idx * 4);
    float xnew = g_zxbcdt[b * D_IN_PROJ + OFF_XBC + c];
    float4 w = *(const float4*)(conv_w + c * 4);

    float v = s.y * w.x + s.z * w.y + s.w * w.z + xnew * w.w + conv_b[c];
    float act = v / (1.0f + expf(-v));  // silu

    float4 ns = make_float4(s.y, s.z, s.w, xnew);
    *(float4*)(conv_out + (size_t)idx * 4) = ns;
    g_xbc[idx] = act;
}

// ---------------- SSM state update + y ----------------
// Block = (b,h). 128 threads = 4 warps. Warp w owns rows p in {w, w+4, ...}.
// Lane l handles n in [4l, 4l+4) via float4.
__global__ void __launch_bounds__(128)
ssm_kernel(const float* __restrict__ ssm_in,
           const float* __restrict__ dt_bias,
           const float* __restrict__ A_log,
           const float* __restrict__ Dparam,
           float* __restrict__ ssm_out) {
    int bh = blockIdx.x;
    int b  = bh >> 6;
    int h  = bh & 63;
    int tid  = threadIdx.x;
    int w    = tid >> 5;
    int lane = tid & 31;

    __shared__ float xs[HEADDIM];
    __shared__ float yp[HEADDIM];

    float dt_raw = g_zxbcdt[b * D_IN_PROJ + OFF_DT + h] + dt_bias[h];
    float dt = (dt_raw > 20.0f) ? dt_raw : log1pf(expf(dt_raw));
    float dA = expf(-dt * expf(A_log[h]));

    const float4* Bv = (const float4*)&g_xbc[b * CONV_DIM + D_SSM];
    const float4* Cv = (const float4*)&g_xbc[b * CONV_DIM + D_SSM + D_STATE];
    float4 B4 = Bv[lane];
    float4 C4 = Cv[lane];
    float4 dtB = make_float4(dt * B4.x, dt * B4.y, dt * B4.z, dt * B4.w);

    if (tid < HEADDIM) xs[tid] = g_xbc[b * CONV_DIM + h * HEADDIM + tid];
    __syncthreads();

    const float4* sin4 = (const float4*)(ssm_in + (size_t)bh * (HEADDIM * D_STATE));
    float4* sout4 = (float4*)(ssm_out + (size_t)bh * (HEADDIM * D_STATE));

#pragma unroll 4
    for (int p = w; p < HEADDIM; p += 4) {
        float xp = xs[p];
        float4 s = sin4[p * 32 + lane];
        float4 sn;
        sn.x = fmaf(s.x, dA, dtB.x * xp);
        sn.y = fmaf(s.y, dA, dtB.y * xp);
        sn.z = fmaf(s.z, dA, dtB.z * xp);
        sn.w = fmaf(s.w, dA, dtB.w * xp);
        sout4[p * 32 + lane] = sn;
        float c = sn.x * C4.x + sn.y * C4.y + sn.z * C4.z + sn.w * C4.w;
#pragma unroll
        for (int o = 16; o; o >>= 1) c += __shfl_xor_sync(0xffffffffu, c, o);
        if (lane == 0) yp[p] = c;
    }
    __syncthreads();

    if (tid < HEADDIM) {
        int p = tid;
        float y = yp[p] + Dparam[h] * xs[p];
        int d = h * HEADDIM + p;
        float z = g_zxbcdt[b * D_IN_PROJ + d];
        float sz = z / (1.0f + expf(-z));  // silu(z)
        g_yact[b * D_SSM + d] = y * sz;
    }
}

// ---------------- Launch ----------------
extern "C" void kernel_launch(void* const* d_in, const int* in_sizes, int n_in,
                              void* d_out, int out_size) {
    const float* hidden     = (const float*)d_in[0];  // [256,1,2048]
    const float* conv_state = (const float*)d_in[1];  // [256,4352,4]
    const float* ssm_state  = (const float*)d_in[2];  // [256,64,64,128]
    const float* in_proj_w  = (const float*)d_in[3];  // [8512,2048]
    const float* conv_w     = (const float*)d_in[4];  // [4352,4]
    const float* conv_b     = (const float*)d_in[5];  // [4352]
    const float* dt_bias    = (const float*)d_in[6];  // [64]
    const float* A_log      = (const float*)d_in[7];  // [64]
    const float* Dp         = (const float*)d_in[8];  // [64]
    const float* out_proj_w = (const float*)d_in[9];  // [2048,4096]

    float* out      = (float*)d_out;
    float* conv_out = out + OUT_ELEMS;
    float* ssm_out  = conv_out + CONV_ELEMS;

    float *zx = nullptr, *yact = nullptr;
    cudaGetSymbolAddress((void**)&zx, g_zxbcdt);
    cudaGetSymbolAddress((void**)&yact, g_yact);

    // 1) in_proj: [256,2048] x [8512,2048]^T -> zxbcdt [256,8512]
    sgemm_nt<BATCH, D_IN_PROJ, D_MODEL, 128, 64, 16, 8, 4>
        <<<dim3(D_IN_PROJ / 64, BATCH / 128), 256>>>(hidden, in_proj_w, zx);

    // 2) conv state roll + conv + silu
    conv_kernel<<<(BATCH * CONV_DIM) / 256, 256>>>(conv_state, conv_w, conv_b, conv_out);

    // 3) SSM state update + gated y
    ssm_kernel<<<BATCH * NHEADS, 128>>>(ssm_state, dt_bias, A_log, Dp, ssm_out);

    // 4) out_proj: [256,4096] x [2048,4096]^T -> out [256,2048]
    sgemm_nt<BATCH, D_MODEL, D_SSM, 64, 64, 16, 4, 4>
        <<<dim3(D_MODEL / 64, BATCH / 64), 256>>>(yact, out_proj_w, out);
}

// round 2
// speedup vs baseline: 1.5898x; 1.5898x over previous
#include <cuda_runtime.h>
#include <cuda_bf16.h>
#include <cstdint>

// ---------------- Problem constants ----------------
#define BATCH    256
#define D_MODEL  2048
#define D_STATE  128
#define D_CONV   4
#define D_SSM    4096
#define NHEADS   64
#define HEADDIM  64
#define CONV_DIM (D_SSM + 2 * D_STATE)           // 4352
#define D_IN_PROJ (2 * D_SSM + 2 * D_STATE + NHEADS) // 8512

#define OFF_XBC  D_SSM
#define OFF_DT   (D_SSM + CONV_DIM)

#define OUT_ELEMS   (BATCH * D_MODEL)
#define CONV_ELEMS  (BATCH * CONV_DIM * D_CONV)

// ---------------- Scratch ----------------
__device__ float g_zxbcdt[BATCH * D_IN_PROJ];
__device__ float g_xbc[BATCH * CONV_DIM];
__device__ float g_yact[BATCH * D_SSM];

// ---------------- bf16 split helpers ----------------
__device__ __forceinline__ uint32_t pack_bf2(__nv_bfloat16 a, __nv_bfloat16 b) {
    __nv_bfloat162 t(a, b);
    return *reinterpret_cast<uint32_t*>(&t);
}
// split (x,y) pair into hi word + lo word
__device__ __forceinline__ void split_pair(float x, float y, uint32_t& hi, uint32_t& lo) {
    __nv_bfloat16 hx = __float2bfloat16_rn(x);
    __nv_bfloat16 hy = __float2bfloat16_rn(y);
    __nv_bfloat16 lx = __float2bfloat16_rn(x - __bfloat162float(hx));
    __nv_bfloat16 ly = __float2bfloat16_rn(y - __bfloat162float(hy));
    hi = pack_bf2(hx, hy);
    lo = pack_bf2(lx, ly);
}

__device__ __forceinline__ void mma_bf16(float* c, const uint32_t* a, const uint32_t* b) {
    asm volatile(
        "mma.sync.aligned.m16n8k16.row.col.f32.bf16.bf16.f32 "
        "{%0,%1,%2,%3}, {%4,%5,%6,%7}, {%8,%9}, {%0,%1,%2,%3};"
        : "+f"(c[0]), "+f"(c[1]), "+f"(c[2]), "+f"(c[3])
        : "r"(a[0]), "r"(a[1]), "r"(a[2]), "r"(a[3]), "r"(b[0]), "r"(b[1]));
}

// ---------------- Tensor-core GEMM with bf16 split-3 ----------------
// C[m,n] = sum_k A[m*K+k] * W[n*K+k]   (A: MxK row-major, W: NxK row-major)
// BK=32, 256 threads (8 warps). Warp tile: 32(m) x WN(n).
template <int M, int N, int K, int BM, int BN>
__global__ void __launch_bounds__(256)
gemm_bf16x3(const float* __restrict__ A, const float* __restrict__ W, float* __restrict__ C) {
    constexpr int BK = 32;
    constexpr int LDW = (BK + 8) / 2;        // smem row stride in 32-bit words (=20)
    constexpr int WARPS_M = BM / 32;
    constexpr int WARPS_N = 8 / WARPS_M;
    constexpr int WN = BN / WARPS_N;
    constexpr int NT = WN / 8;               // n mma tiles per warp
    constexpr int A_LD = BM / 32;            // float4 loads per thread for A
    constexpr int B_LD = BN / 32;

    __shared__ uint32_t Ah[BM * LDW], Al[BM * LDW];
    __shared__ uint32_t Bh[BN * LDW], Bl[BN * LDW];

    const int tid  = threadIdx.x;
    const int lane = tid & 31;
    const int wid  = tid >> 5;
    const int warp_m = wid / WARPS_N;
    const int warp_n = wid % WARPS_N;
    const int mBase = blockIdx.y * BM;
    const int nBase = blockIdx.x * BN;

    float acc[2][NT][4];
#pragma unroll
    for (int mt = 0; mt < 2; mt++)
#pragma unroll
        for (int nt = 0; nt < NT; nt++)
#pragma unroll
            for (int i = 0; i < 4; i++) acc[mt][nt][i] = 0.0f;

    float4 aR[A_LD], bR[B_LD];

    auto ldA = [&](int kk) {
#pragma unroll
        for (int i = 0; i < A_LD; i++) {
            int id = tid + i * 256;
            int r = id >> 3, c = id & 7;
            aR[i] = *(const float4*)(A + (size_t)(mBase + r) * K + kk + c * 4);
        }
    };
    auto ldB = [&](int kk) {
#pragma unroll
        for (int i = 0; i < B_LD; i++) {
            int id = tid + i * 256;
            int r = id >> 3, c = id & 7;
            bR[i] = *(const float4*)(W + (size_t)(nBase + r) * K + kk + c * 4);
        }
    };
    auto stA = [&]() {
#pragma unroll
        for (int i = 0; i < A_LD; i++) {
            int id = tid + i * 256;
            int r = id >> 3, c = id & 7;
            uint32_t h0, l0, h1, l1;
            split_pair(aR[i].x, aR[i].y, h0, l0);
            split_pair(aR[i].z, aR[i].w, h1, l1);
            int base = r * LDW + c * 2;
            Ah[base] = h0; Ah[base + 1] = h1;
            Al[base] = l0; Al[base + 1] = l1;
        }
    };
    auto stB = [&]() {
#pragma unroll
        for (int i = 0; i < B_LD; i++) {
            int id = tid + i * 256;
            int r = id >> 3, c = id & 7;
            uint32_t h0, l0, h1, l1;
            split_pair(bR[i].x, bR[i].y, h0, l0);
            split_pair(bR[i].z, bR[i].w, h1, l1);
            int base = r * LDW + c * 2;
            Bh[base] = h0; Bh[base + 1] = h1;
            Bl[base] = l0; Bl[base + 1] = l1;
        }
    };

    ldA(0); ldB(0);

    for (int kk = 0; kk < K; kk += BK) {
        stA(); stB();
        __syncthreads();
        if (kk + BK < K) { ldA(kk + BK); ldB(kk + BK); }

#pragma unroll
        for (int k0 = 0; k0 < BK; k0 += 16) {
            const int kw = (k0 >> 1) + (lane & 3);
            uint32_t ah[2][4], al[2][4];
#pragma unroll
            for (int mt = 0; mt < 2; mt++) {
                int row = warp_m * 32 + mt * 16 + (lane >> 2);
                int base = row * LDW + kw;
                ah[mt][0] = Ah[base];
                ah[mt][1] = Ah[base + 8 * LDW];
                ah[mt][2] = Ah[base + 4];
                ah[mt][3] = Ah[base + 8 * LDW + 4];
                al[mt][0] = Al[base];
                al[mt][1] = Al[base + 8 * LDW];
                al[mt][2] = Al[base + 4];
                al[mt][3] = Al[base + 8 * LDW + 4];
            }
            uint32_t bh[NT][2], bl[NT][2];
#pragma unroll
            for (int nt = 0; nt < NT; nt++) {
                int n = warp_n * WN + nt * 8 + (lane >> 2);
                int base = n * LDW + kw;
                bh[nt][0] = Bh[base];
                bh[nt][1] = Bh[base + 4];
                bl[nt][0] = Bl[base];
                bl[nt][1] = Bl[base + 4];
            }
#pragma unroll
            for (int mt = 0; mt < 2; mt++)
#pragma unroll
                for (int nt = 0; nt < NT; nt++) {
                    mma_bf16(acc[mt][nt], ah[mt], bh[nt]);
                    mma_bf16(acc[mt][nt], ah[mt], bl[nt]);
                    mma_bf16(acc[mt][nt], al[mt], bh[nt]);
                }
        }
        __syncthreads();
    }

    // Epilogue
#pragma unroll
    for (int mt = 0; mt < 2; mt++)
#pragma unroll
        for (int nt = 0; nt < NT; nt++) {
            int r = mBase + warp_m * 32 + mt * 16 + (lane >> 2);
            int c = nBase + warp_n * WN + nt * 8 + (lane & 3) * 2;
            *(float2*)(C + (size_t)r * N + c)       = make_float2(acc[mt][nt][0], acc[mt][nt][1]);
            *(float2*)(C + (size_t)(r + 8) * N + c) = make_float2(acc[mt][nt][2], acc[mt][nt][3]);
        }
}

// ---------------- Conv: roll state, 4-tap conv + bias, SiLU ----------------
__global__ void conv_kernel(const float* __restrict__ conv_in,
                            const float* __restrict__ conv_w,
                            const float* __restrict__ conv_b,
                            float* __restrict__ conv_out) {
    int idx = blockIdx.x * blockDim.x + threadIdx.x;
    if (idx >= BATCH * CONV_DIM) return;
    int b = idx / CONV_DIM;
    int c = idx % CONV_DIM;

    float4 s = *(const float4*)(conv_in + (size_t)idx * 4);
    float xnew = g_zxbcdt[b * D_IN_PROJ + OFF_XBC + c];
    float4 w = *(const float4*)(conv_w + c * 4);

    float v = s.y * w.x + s.z * w.y + s.w * w.z + xnew * w.w + conv_b[c];
    float act = v / (1.0f + expf(-v));

    float4 ns = make_float4(s.y, s.z, s.w, xnew);
    *(float4*)(conv_out + (size_t)idx * 4) = ns;
    g_xbc[idx] = act;
}

// ---------------- SSM state update + y ----------------
__global__ void __launch_bounds__(128)
ssm_kernel(const float* __restrict__ ssm_in,
           const float* __restrict__ dt_bias,
           const float* __restrict__ A_log,
           const float* __restrict__ Dparam,
           float* __restrict__ ssm_out) {
    int bh = blockIdx.x;
    int b  = bh >> 6;
    int h  = bh & 63;
    int tid  = threadIdx.x;
    int w    = tid >> 5;
    int lane = tid & 31;

    __shared__ float xs[HEADDIM];
    __shared__ float yp[HEADDIM];

    float dt_raw = g_zxbcdt[b * D_IN_PROJ + OFF_DT + h] + dt_bias[h];
    float dt = (dt_raw > 20.0f) ? dt_raw : log1pf(expf(dt_raw));
    float dA = expf(-dt * expf(A_log[h]));

    const float4* Bv = (const float4*)&g_xbc[b * CONV_DIM + D_SSM];
    const float4* Cv = (const float4*)&g_xbc[b * CONV_DIM + D_SSM + D_STATE];
    float4 B4 = Bv[lane];
    float4 C4 = Cv[lane];
    float4 dtB = make_float4(dt * B4.x, dt * B4.y, dt * B4.z, dt * B4.w);

    if (tid < HEADDIM) xs[tid] = g_xbc[b * CONV_DIM + h * HEADDIM + tid];
    __syncthreads();

    const float4* sin4 = (const float4*)(ssm_in + (size_t)bh * (HEADDIM * D_STATE));
    float4* sout4 = (float4*)(ssm_out + (size_t)bh * (HEADDIM * D_STATE));

#pragma unroll 4
    for (int p = w; p < HEADDIM; p += 4) {
        float xp = xs[p];
        float4 s = sin4[p * 32 + lane];
        float4 sn;
        sn.x = fmaf(s.x, dA, dtB.x * xp);
        sn.y = fmaf(s.y, dA, dtB.y * xp);
        sn.z = fmaf(s.z, dA, dtB.z * xp);
        sn.w = fmaf(s.w, dA, dtB.w * xp);
        sout4[p * 32 + lane] = sn;
        float c = sn.x * C4.x + sn.y * C4.y + sn.z * C4.z + sn.w * C4.w;
#pragma unroll
        for (int o = 16; o; o >>= 1) c += __shfl_xor_sync(0xffffffffu, c, o);
        if (lane == 0) yp[p] = c;
    }
    __syncthreads();

    if (tid < HEADDIM) {
        int p = tid;
        float y = yp[p] + Dparam[h] * xs[p];
        int d = h * HEADDIM + p;
        float z = g_zxbcdt[b * D_IN_PROJ + d];
        float sz = z / (1.0f + expf(-z));
        g_yact[b * D_SSM + d] = y * sz;
    }
}

// ---------------- Launch ----------------
extern "C" void kernel_launch(void* const* d_in, const int* in_sizes, int n_in,
                              void* d_out, int out_size) {
    const float* hidden     = (const float*)d_in[0];
    const float* conv_state = (const float*)d_in[1];
    const float* ssm_state  = (const float*)d_in[2];
    const float* in_proj_w  = (const float*)d_in[3];
    const float* conv_w     = (const float*)d_in[4];
    const float* conv_b     = (const float*)d_in[5];
    const float* dt_bias    = (const float*)d_in[6];
    const float* A_log      = (const float*)d_in[7];
    const float* Dp         = (const float*)d_in[8];
    const float* out_proj_w = (const float*)d_in[9];

    float* out      = (float*)d_out;
    float* conv_out = out + OUT_ELEMS;
    float* ssm_out  = conv_out + CONV_ELEMS;

    float *zx = nullptr, *yact = nullptr;
    cudaGetSymbolAddress((void**)&zx, g_zxbcdt);
    cudaGetSymbolAddress((void**)&yact, g_yact);

    // 1) in_proj: [256,2048] x [8512,2048]^T -> zxbcdt [256,8512]
    gemm_bf16x3<BATCH, D_IN_PROJ, D_MODEL, 128, 64>
        <<<dim3(D_IN_PROJ / 64, BATCH / 128), 256>>>(hidden, in_proj_w, zx);

    // 2) conv state roll + conv + silu
    conv_kernel<<<(BATCH * CONV_DIM) / 256, 256>>>(conv_state, conv_w, conv_b, conv_out);

    // 3) SSM state update + gated y
    ssm_kernel<<<BATCH * NHEADS, 128>>>(ssm_state, dt_bias, A_log, Dp, ssm_out);

    // 4) out_proj: [256,4096] x [2048,4096]^T -> out [256,2048]
    gemm_bf16x3<BATCH, D_MODEL, D_SSM, 64, 64>
        <<<dim3(D_MODEL / 64, BATCH / 64), 256>>>(yact, out_proj_w, out);
}